// round 2
// baseline (speedup 1.0000x reference)
#include <cuda_runtime.h>

// PAM_Module_Dep: dual-modality position attention.
// B=4, C=512, H=W=64 -> N=4096, CQ=64, D=2*CQ=128.
//
// Pipeline:
//  1) projections (conv1x1 == GEMM):  q[b,0:64]=Wq x_b, q[b,64:128]=Wqd dep_b (+bias)
//     same for k; v = Wv x_b (+bias)
//  2) energy[b,i,j] = sum_d q[b,d,i] k[b,d,j]         (TN GEMM, K=128)
//  3) attn = softmax_j(energy)                         (row softmax, in place)
//  4) out[b,c,i] = sum_j v[b,c,j] attn[i,j]; final = gamma*out + x  (NT GEMM, K=4096)
//
// All fp32 (softmax logit sigma ~14.5: low-precision GEMM inputs would blow
// the 1e-3 rel-err budget through the exponential). Double-buffered smem
// pipeline: one barrier per K-tile, global loads overlapped with FFMA.

#define BATCH 4
#define CCH   512
#define NPIX  4096
#define DQK   128
#define CQ    64

// Scratch (device globals: allocation-guard-safe).
__device__ float g_q[BATCH * DQK * NPIX];                    // 8 MB
__device__ float g_k[BATCH * DQK * NPIX];                    // 8 MB
__device__ float g_v[BATCH * CCH * NPIX];                    // 33.5 MB
__device__ float g_e[(size_t)BATCH * NPIX * NPIX];           // 268 MB

// ---------------------------------------------------------------------------
// Tiled fp32 GEMM, register-staged double-buffered smem.
//   C[m,n] = sum_k A(m,k) * B(k,n)   per batch (blockIdx.z)
// A_KM: A stored K-major [K][M] (lda = M-stride), else row-major [M][K].
// B_KM: B stored K-major [K][N], else row-major [N][K].
// EPI: 0 = plain store, 1 = +bias[m], 2 = gamma*acc + X[m,n] (X layout == C).
// ---------------------------------------------------------------------------
template <int BM, int BN, int BK, int TM, int TN, bool A_KM, bool B_KM, int EPI>
__global__ __launch_bounds__(256, 2) void gemm_k(
    const float* __restrict__ A, const float* __restrict__ B,
    float* __restrict__ C,
    int K, int lda, int ldb, int ldc,
    long long sA, long long sB, long long sC,
    const float* __restrict__ bias,
    const float* __restrict__ X, long long sX,
    const float* __restrict__ gamma)
{
    constexpr int NT = 256;
    static_assert((BM / TM) * (BN / TN) == NT, "thread tiling mismatch");
    constexpr int ALD = BM * BK / 4 / NT;   // float4 loads per thread (A)
    constexpr int BLD = BN * BK / 4 / NT;   // float4 loads per thread (B)
    static_assert(ALD >= 1 && BLD >= 1, "tile too small");

    __shared__ float As[2][BK][BM + 4];
    __shared__ float Bs[2][BK][BN + 4];

    const int b = blockIdx.z;
    A += (long long)b * sA;
    B += (long long)b * sB;
    C += (long long)b * sC;

    const int m0 = blockIdx.y * BM;
    const int n0 = blockIdx.x * BN;
    const int tid = threadIdx.x;
    const int tx = tid % (BN / TN);
    const int ty = tid / (BN / TN);

    float4 ra[ALD], rb[BLD];

    auto loadA = [&](int k0) {
#pragma unroll
        for (int it = 0; it < ALD; ++it) {
            int idx = tid + it * NT;
            if constexpr (A_KM) {
                int r = idx / (BM / 4), c = idx % (BM / 4);
                ra[it] = *reinterpret_cast<const float4*>(
                    &A[(long long)(k0 + r) * lda + m0 + c * 4]);
            } else {
                int r = idx / (BK / 4), c = idx % (BK / 4);
                ra[it] = *reinterpret_cast<const float4*>(
                    &A[(long long)(m0 + r) * lda + k0 + c * 4]);
            }
        }
    };
    auto stashA = [&](int buf) {
#pragma unroll
        for (int it = 0; it < ALD; ++it) {
            int idx = tid + it * NT;
            if constexpr (A_KM) {
                int r = idx / (BM / 4), c = idx % (BM / 4);
                *reinterpret_cast<float4*>(&As[buf][r][c * 4]) = ra[it];
            } else {
                int r = idx / (BK / 4), c = idx % (BK / 4);
                As[buf][c * 4 + 0][r] = ra[it].x;
                As[buf][c * 4 + 1][r] = ra[it].y;
                As[buf][c * 4 + 2][r] = ra[it].z;
                As[buf][c * 4 + 3][r] = ra[it].w;
            }
        }
    };
    auto loadB = [&](int k0) {
#pragma unroll
        for (int it = 0; it < BLD; ++it) {
            int idx = tid + it * NT;
            if constexpr (B_KM) {
                int r = idx / (BN / 4), c = idx % (BN / 4);
                rb[it] = *reinterpret_cast<const float4*>(
                    &B[(long long)(k0 + r) * ldb + n0 + c * 4]);
            } else {
                int r = idx / (BK / 4), c = idx % (BK / 4);
                rb[it] = *reinterpret_cast<const float4*>(
                    &B[(long long)(n0 + r) * ldb + k0 + c * 4]);
            }
        }
    };
    auto stashB = [&](int buf) {
#pragma unroll
        for (int it = 0; it < BLD; ++it) {
            int idx = tid + it * NT;
            if constexpr (B_KM) {
                int r = idx / (BN / 4), c = idx % (BN / 4);
                *reinterpret_cast<float4*>(&Bs[buf][r][c * 4]) = rb[it];
            } else {
                int r = idx / (BK / 4), c = idx % (BK / 4);
                Bs[buf][c * 4 + 0][r] = rb[it].x;
                Bs[buf][c * 4 + 1][r] = rb[it].y;
                Bs[buf][c * 4 + 2][r] = rb[it].z;
                Bs[buf][c * 4 + 3][r] = rb[it].w;
            }
        }
    };

    float acc[TM][TN];
#pragma unroll
    for (int i = 0; i < TM; i++)
#pragma unroll
        for (int j = 0; j < TN; j++) acc[i][j] = 0.f;

    // prologue: tile 0 -> buffer 0
    loadA(0); loadB(0);
    stashA(0); stashB(0);
    __syncthreads();

    const int nTiles = K / BK;
    for (int t = 0; t < nTiles; ++t) {
        const int cur = t & 1, nxt = cur ^ 1;
        const bool more = (t + 1 < nTiles);
        if (more) { loadA((t + 1) * BK); loadB((t + 1) * BK); }

#pragma unroll
        for (int kk = 0; kk < BK; kk++) {
            float a[TM], bb[TN];
#pragma unroll
            for (int i = 0; i < TM; i++) a[i] = As[cur][kk][ty * TM + i];
#pragma unroll
            for (int j = 0; j < TN; j++) bb[j] = Bs[cur][kk][tx * TN + j];
#pragma unroll
            for (int i = 0; i < TM; i++)
#pragma unroll
                for (int j = 0; j < TN; j++)
                    acc[i][j] = fmaf(a[i], bb[j], acc[i][j]);
        }

        if (more) {
            stashA(nxt); stashB(nxt);
            __syncthreads();
        }
    }

    // ---- epilogue ----
    float g = 0.f;
    const float* Xb = nullptr;
    if constexpr (EPI == 2) {
        g = gamma[0];
        Xb = X + (long long)b * sX;
    }
#pragma unroll
    for (int i = 0; i < TM; i++) {
        int m = m0 + ty * TM + i;
        float bi = 0.f;
        if constexpr (EPI == 1) bi = bias[m];
#pragma unroll
        for (int j = 0; j < TN; j++) {
            int n = n0 + tx * TN + j;
            long long off = (long long)m * ldc + n;
            float v = acc[i][j];
            if constexpr (EPI == 1) v += bi;
            if constexpr (EPI == 2) v = fmaf(g, v, Xb[off]);
            C[off] = v;
        }
    }
}

// ---------------------------------------------------------------------------
// Row softmax over 4096 elements, in place. One CTA (256 threads) per row,
// 16 values per thread held in registers (coalesced strided access).
// ---------------------------------------------------------------------------
__global__ __launch_bounds__(256) void softmax_k(float* __restrict__ e)
{
    const long long row = blockIdx.x;
    float* p = e + row * (long long)NPIX;
    const int tid = threadIdx.x;

    float v[16];
#pragma unroll
    for (int k = 0; k < 16; k++) v[k] = p[tid + k * 256];

    float mx = -1e30f;
#pragma unroll
    for (int k = 0; k < 16; k++) mx = fmaxf(mx, v[k]);
#pragma unroll
    for (int o = 16; o > 0; o >>= 1) mx = fmaxf(mx, __shfl_xor_sync(0xffffffffu, mx, o));

    __shared__ float redm[8];
    __shared__ float reds[8];
    if ((tid & 31) == 0) redm[tid >> 5] = mx;
    __syncthreads();
    mx = redm[0];
#pragma unroll
    for (int i = 1; i < 8; i++) mx = fmaxf(mx, redm[i]);

    float s = 0.f;
#pragma unroll
    for (int k = 0; k < 16; k++) {
        v[k] = __expf(v[k] - mx);
        s += v[k];
    }
#pragma unroll
    for (int o = 16; o > 0; o >>= 1) s += __shfl_xor_sync(0xffffffffu, s, o);
    if ((tid & 31) == 0) reds[tid >> 5] = s;
    __syncthreads();
    s = 0.f;
#pragma unroll
    for (int i = 0; i < 8; i++) s += reds[i];

    const float inv = 1.f / s;
#pragma unroll
    for (int k = 0; k < 16; k++) p[tid + k * 256] = v[k] * inv;
}

// ---------------------------------------------------------------------------
extern "C" void kernel_launch(void* const* d_in, const int* in_sizes, int n_in,
                              void* d_out, int out_size)
{
    const float* x     = (const float*)d_in[0];
    const float* dep   = (const float*)d_in[1];
    const float* wq    = (const float*)d_in[2];
    const float* bq    = (const float*)d_in[3];
    const float* wqd   = (const float*)d_in[4];
    const float* bqd   = (const float*)d_in[5];
    const float* wk    = (const float*)d_in[6];
    const float* bk    = (const float*)d_in[7];
    const float* wkd   = (const float*)d_in[8];
    const float* bkd   = (const float*)d_in[9];
    const float* wv    = (const float*)d_in[10];
    const float* bv    = (const float*)d_in[11];
    const float* gamma = (const float*)d_in[12];
    float* out = (float*)d_out;

    float *qp, *kp, *vp, *ep;
    cudaGetSymbolAddress((void**)&qp, g_q);
    cudaGetSymbolAddress((void**)&kp, g_k);
    cudaGetSymbolAddress((void**)&vp, g_v);
    cudaGetSymbolAddress((void**)&ep, g_e);

    const long long sIn  = (long long)CCH * NPIX;   // x / dep / v / out batch stride
    const long long sQK  = (long long)DQK * NPIX;   // q / k batch stride
    const long long sE   = (long long)NPIX * NPIX;  // energy batch stride

    dim3 blk(256);

    // ---- projections: W (row-major [M][K=512]) x in_b (K-major [512][4096]) + bias
    {
        dim3 gq(NPIX / 128, CQ / 64, BATCH);
        gemm_k<64, 128, 16, 4, 8, false, true, 1><<<gq, blk>>>(
            wq, x, qp, CCH, CCH, NPIX, NPIX, 0, sIn, sQK, bq, nullptr, 0, nullptr);
        gemm_k<64, 128, 16, 4, 8, false, true, 1><<<gq, blk>>>(
            wqd, dep, qp + (long long)CQ * NPIX, CCH, CCH, NPIX, NPIX, 0, sIn, sQK, bqd,
            nullptr, 0, nullptr);
        gemm_k<64, 128, 16, 4, 8, false, true, 1><<<gq, blk>>>(
            wk, x, kp, CCH, CCH, NPIX, NPIX, 0, sIn, sQK, bk, nullptr, 0, nullptr);
        gemm_k<64, 128, 16, 4, 8, false, true, 1><<<gq, blk>>>(
            wkd, dep, kp + (long long)CQ * NPIX, CCH, CCH, NPIX, NPIX, 0, sIn, sQK, bkd,
            nullptr, 0, nullptr);
        dim3 gv(NPIX / 128, CCH / 64, BATCH);
        gemm_k<64, 128, 16, 4, 8, false, true, 1><<<gv, blk>>>(
            wv, x, vp, CCH, CCH, NPIX, NPIX, 0, sIn, sIn, bv, nullptr, 0, nullptr);
    }

    // ---- energy[b,i,j] = sum_d q[b,d,i] k[b,d,j]   (A,B both K-major, K=128)
    {
        dim3 ge(NPIX / 128, NPIX / 128, BATCH);
        gemm_k<128, 128, 16, 8, 8, true, true, 0><<<ge, blk>>>(
            qp, kp, ep, DQK, NPIX, NPIX, NPIX, sQK, sQK, sE, nullptr, nullptr, 0, nullptr);
    }

    // ---- softmax over rows of energy (in place) ----
    softmax_k<<<BATCH * NPIX, blk>>>(ep);

    // ---- out[b,c,i] = sum_j v[b,c,j] attn[b,i,j]; final = gamma*out + x ----
    {
        dim3 go(NPIX / 128, CCH / 128, BATCH);
        gemm_k<128, 128, 16, 8, 8, false, false, 2><<<go, blk>>>(
            vp, ep, out, NPIX, NPIX, NPIX, NPIX, sIn, sE, sIn, nullptr, x, sIn, gamma);
    }
}

// round 5
// speedup vs baseline: 1.8360x; 1.8360x over previous
#include <cuda_runtime.h>
#include <cuda_bf16.h>
#include <cstdint>

// PAM_Module_Dep attention. B=4, C=512, N=4096, D=128.
// R5 == R4 (audited, unchanged; R4 never ran due to broker timeout).
// tcgen05 is NOT compilable here (harness PTX targets sm_103 without 'a');
// tensor cores via mma.sync HMMA. energy + out GEMMs: bf16 split-precision
// (hi/lo, 3 accumulating passes, fp32 accumulators) -> ~1e-5 accuracy.
// Projections fp32 FFMA.

#define BATCH 4
#define CCH   512
#define NPIX  4096
#define DQK   128
#define CQ    64

// ---- device-global scratch (allocation-guard-safe) ----
__device__ float g_q[BATCH * DQK * NPIX];                    // q [b][d][i]
__device__ float g_k[BATCH * DQK * NPIX];
__device__ float g_v[BATCH * CCH * NPIX];
__device__ float g_e[(size_t)BATCH * NPIX * NPIX];           // energy fp32
__device__ __nv_bfloat16 g_qh[BATCH * NPIX * DQK];           // q^T hi [b][i][d]
__device__ __nv_bfloat16 g_ql[BATCH * NPIX * DQK];
__device__ __nv_bfloat16 g_kh[BATCH * NPIX * DQK];
__device__ __nv_bfloat16 g_kl[BATCH * NPIX * DQK];
__device__ __nv_bfloat16 g_ah[(size_t)BATCH * NPIX * NPIX];  // attn hi [b][i][j]
__device__ __nv_bfloat16 g_al[(size_t)BATCH * NPIX * NPIX];
__device__ __nv_bfloat16 g_vh[BATCH * CCH * NPIX];           // v hi [b][c][j]
__device__ __nv_bfloat16 g_vl[BATCH * CCH * NPIX];

__device__ __forceinline__ uint32_t smem_u32(const void* p) {
    uint32_t a;
    asm("{ .reg .u64 t; cvta.to.shared.u64 t, %1; cvt.u32.u64 %0, t; }"
        : "=r"(a) : "l"(p));
    return a;
}
#define LDSM4(r0, r1, r2, r3, addr)                                           \
    asm volatile("ldmatrix.sync.aligned.m8n8.x4.shared.b16 {%0,%1,%2,%3}, [%4];" \
                 : "=r"(r0), "=r"(r1), "=r"(r2), "=r"(r3) : "r"(addr))
#define MMA16816(d, a, b0, b1)                                                \
    asm volatile("mma.sync.aligned.m16n8k16.row.col.f32.bf16.bf16.f32 "       \
                 "{%0,%1,%2,%3}, {%4,%5,%6,%7}, {%8,%9}, {%0,%1,%2,%3};"      \
                 : "+f"((d)[0]), "+f"((d)[1]), "+f"((d)[2]), "+f"((d)[3])     \
                 : "r"((a)[0]), "r"((a)[1]), "r"((a)[2]), "r"((a)[3]),        \
                   "r"(b0), "r"(b1))

// ============================================================================
// bf16 split-precision GEMM via mma.sync.
//   C[m,n] = sum over passes {(Ah,Bh),(Al,Bh),(Ah,Bl)} of sum_k A[m,k]*B[n,k]
// A: M x K row-major bf16 (K contiguous); B: N x K row-major bf16.
// CTA 128x128, 8 warps (4 M x 2 N), warp tile 32x64, K-stage 32, dbl-buffered.
// EPI: 0 = plain fp32 store; 2 = gamma*acc + X.
// ============================================================================
#define STR 40                      // smem row stride in halves (80 B)
#define STAGE_B 10240               // 128 rows * 80 B
#define MMASMEM (4 * STAGE_B)       // A0 B0 A1 B1

template <int EPI>
__global__ __launch_bounds__(256, 2) void mma_gemm(
    const __nv_bfloat16* __restrict__ Ah, const __nv_bfloat16* __restrict__ Al,
    const __nv_bfloat16* __restrict__ Bh, const __nv_bfloat16* __restrict__ Bl,
    float* __restrict__ C, int Ktot,
    long long sA, long long sB, long long sC,
    const float* __restrict__ X, const float* __restrict__ gam)
{
    extern __shared__ char smem[];
    const uint32_t sb = smem_u32(smem);
    const int tid = threadIdx.x, wid = tid >> 5, lane = tid & 31;
    const int wm = wid & 3, wn = wid >> 2;
    const int b = blockIdx.z;
    const int m0 = blockIdx.x * 128;
    const int n0 = blockIdx.y * 128;

    Ah += (long long)b * sA; Al += (long long)b * sA;
    Bh += (long long)b * sB; Bl += (long long)b * sB;
    C  += (long long)b * sC;

    const __nv_bfloat16* PA[3] = {Ah, Al, Ah};
    const __nv_bfloat16* PB[3] = {Bh, Bh, Bl};
    const int spp = Ktot / 32;          // stages per pass
    const int T = 3 * spp;

    // per-thread global-load geometry: 2 chunks of 16B per operand per stage
    const int lr0 = tid >> 2;           // row for chunk 0 (0..63)
    const int lu  = tid & 3;            // 16B chunk within 64B row
    float4 ra[2], rb[2];

    auto gload = [&](int t) {
        const __nv_bfloat16* A = PA[t / spp];
        const __nv_bfloat16* B = PB[t / spp];
        const int kg = (t % spp) * 32;
#pragma unroll
        for (int it = 0; it < 2; ++it) {
            int r = lr0 + it * 64;
            ra[it] = *reinterpret_cast<const float4*>(
                A + (long long)(m0 + r) * Ktot + kg + lu * 8);
            rb[it] = *reinterpret_cast<const float4*>(
                B + (long long)(n0 + r) * Ktot + kg + lu * 8);
        }
    };
    auto stash = [&](int buf) {
        char* pa = smem + buf * (2 * STAGE_B);
        char* pb = pa + STAGE_B;
#pragma unroll
        for (int it = 0; it < 2; ++it) {
            int r = lr0 + it * 64;
            *reinterpret_cast<float4*>(pa + r * 80 + lu * 16) = ra[it];
            *reinterpret_cast<float4*>(pb + r * 80 + lu * 16) = rb[it];
        }
    };

    float acc[2][8][4];
#pragma unroll
    for (int i = 0; i < 2; i++)
#pragma unroll
        for (int j = 0; j < 8; j++)
#pragma unroll
            for (int r = 0; r < 4; r++) acc[i][j][r] = 0.f;

    gload(0); stash(0);
    __syncthreads();

    const int lrow = lane & 15;         // ldmatrix row within 16
    const int lcol = (lane >> 4) * 8;   // halves offset within k16

    for (int t = 0; t < T; ++t) {
        const int cur = t & 1;
        if (t + 1 < T) gload(t + 1);

        const uint32_t baseA = sb + cur * (2 * STAGE_B);
        const uint32_t baseB = baseA + STAGE_B;
#pragma unroll
        for (int s = 0; s < 2; ++s) {
            uint32_t a[2][4], bf[4][4];
#pragma unroll
            for (int mt = 0; mt < 2; ++mt) {
                uint32_t ad = baseA +
                    ((wm * 32 + mt * 16 + lrow) * STR + s * 16 + lcol) * 2;
                LDSM4(a[mt][0], a[mt][1], a[mt][2], a[mt][3], ad);
            }
#pragma unroll
            for (int p = 0; p < 4; ++p) {
                uint32_t bd = baseB +
                    ((wn * 64 + p * 16 + lrow) * STR + s * 16 + lcol) * 2;
                LDSM4(bf[p][0], bf[p][1], bf[p][2], bf[p][3], bd);
            }
#pragma unroll
            for (int mt = 0; mt < 2; ++mt)
#pragma unroll
                for (int p = 0; p < 4; ++p) {
                    MMA16816(acc[mt][2 * p + 0], a[mt], bf[p][0], bf[p][2]);
                    MMA16816(acc[mt][2 * p + 1], a[mt], bf[p][1], bf[p][3]);
                }
        }
        if (t + 1 < T) {
            stash(cur ^ 1);
            __syncthreads();
        }
    }

    // epilogue: D frag (g=lane/4, c=lane%4): d0,d1 @ (g, 2c..), d2,d3 @ (g+8)
    const float g = (EPI == 2) ? gam[0] : 0.f;
    const float* Xb = (EPI == 2) ? X + (long long)b * sC : nullptr;
#pragma unroll
    for (int mt = 0; mt < 2; ++mt)
#pragma unroll
        for (int nt = 0; nt < 8; ++nt) {
            int row0 = m0 + wm * 32 + mt * 16 + (lane >> 2);
            int col  = n0 + wn * 64 + nt * 8 + (lane & 3) * 2;
#pragma unroll
            for (int h = 0; h < 2; ++h) {
                long long off = (long long)(row0 + h * 8) * NPIX + col;
                float2 v = make_float2(acc[mt][nt][2 * h], acc[mt][nt][2 * h + 1]);
                if (EPI == 2) {
                    float2 xx = *reinterpret_cast<const float2*>(Xb + off);
                    v.x = fmaf(g, v.x, xx.x);
                    v.y = fmaf(g, v.y, xx.y);
                }
                *reinterpret_cast<float2*>(C + off) = v;
            }
        }
}

// ============================================================================
// fp32 tiled GEMM (double-buffered) — projections only.
// ============================================================================
template <int BM, int BN, int BK, int TM, int TN>
__global__ __launch_bounds__(256, 2) void gemm_k(
    const float* __restrict__ A, const float* __restrict__ B,
    float* __restrict__ C,
    int K, int lda, int ldb, int ldc,
    long long sA, long long sB, long long sC,
    const float* __restrict__ bias)
{
    constexpr int NT = 256;
    static_assert((BM / TM) * (BN / TN) == NT, "tiling");
    constexpr int ALD = BM * BK / 4 / NT;
    constexpr int BLD = BN * BK / 4 / NT;

    __shared__ float As[2][BK][BM + 4];
    __shared__ float Bs[2][BK][BN + 4];

    const int b = blockIdx.z;
    A += (long long)b * sA;
    B += (long long)b * sB;
    C += (long long)b * sC;

    const int m0 = blockIdx.y * BM;
    const int n0 = blockIdx.x * BN;
    const int tid = threadIdx.x;
    const int tx = tid % (BN / TN);
    const int ty = tid / (BN / TN);

    float4 ra[ALD], rb[BLD];

    auto loadA = [&](int k0) {   // A row-major [M][K]
#pragma unroll
        for (int it = 0; it < ALD; ++it) {
            int idx = tid + it * NT;
            int r = idx / (BK / 4), c = idx % (BK / 4);
            ra[it] = *reinterpret_cast<const float4*>(
                &A[(long long)(m0 + r) * lda + k0 + c * 4]);
        }
    };
    auto stashA = [&](int buf) {
#pragma unroll
        for (int it = 0; it < ALD; ++it) {
            int idx = tid + it * NT;
            int r = idx / (BK / 4), c = idx % (BK / 4);
            As[buf][c * 4 + 0][r] = ra[it].x;
            As[buf][c * 4 + 1][r] = ra[it].y;
            As[buf][c * 4 + 2][r] = ra[it].z;
            As[buf][c * 4 + 3][r] = ra[it].w;
        }
    };
    auto loadB = [&](int k0) {   // B K-major [K][N]
#pragma unroll
        for (int it = 0; it < BLD; ++it) {
            int idx = tid + it * NT;
            int r = idx / (BN / 4), c = idx % (BN / 4);
            rb[it] = *reinterpret_cast<const float4*>(
                &B[(long long)(k0 + r) * ldb + n0 + c * 4]);
        }
    };
    auto stashB = [&](int buf) {
#pragma unroll
        for (int it = 0; it < BLD; ++it) {
            int idx = tid + it * NT;
            int r = idx / (BN / 4), c = idx % (BN / 4);
            *reinterpret_cast<float4*>(&Bs[buf][r][c * 4]) = rb[it];
        }
    };

    float acc[TM][TN];
#pragma unroll
    for (int i = 0; i < TM; i++)
#pragma unroll
        for (int j = 0; j < TN; j++) acc[i][j] = 0.f;

    loadA(0); loadB(0);
    stashA(0); stashB(0);
    __syncthreads();

    const int nTiles = K / BK;
    for (int t = 0; t < nTiles; ++t) {
        const int cur = t & 1;
        const bool more = (t + 1 < nTiles);
        if (more) { loadA((t + 1) * BK); loadB((t + 1) * BK); }

#pragma unroll
        for (int kk = 0; kk < BK; kk++) {
            float a[TM], bb[TN];
#pragma unroll
            for (int i = 0; i < TM; i++) a[i] = As[cur][kk][ty * TM + i];
#pragma unroll
            for (int j = 0; j < TN; j++) bb[j] = Bs[cur][kk][tx * TN + j];
#pragma unroll
            for (int i = 0; i < TM; i++)
#pragma unroll
                for (int j = 0; j < TN; j++)
                    acc[i][j] = fmaf(a[i], bb[j], acc[i][j]);
        }
        if (more) {
            stashA(cur ^ 1); stashB(cur ^ 1);
            __syncthreads();
        }
    }

#pragma unroll
    for (int i = 0; i < TM; i++) {
        int m = m0 + ty * TM + i;
        float bi = bias[m];
#pragma unroll
        for (int j = 0; j < TN; j++) {
            int n = n0 + tx * TN + j;
            C[(long long)m * ldc + n] = acc[i][j] + bi;
        }
    }
}

// ---------------------------------------------------------------------------
// transpose + hi/lo split: src fp32 [D][N] -> dh/dl bf16 [N][D]  (per batch)
// ---------------------------------------------------------------------------
__global__ __launch_bounds__(256) void tsplit_k(
    const float* __restrict__ src, __nv_bfloat16* __restrict__ dh,
    __nv_bfloat16* __restrict__ dl)
{
    __shared__ float t[32][33];
    const long long sQK = (long long)DQK * NPIX;
    const int b = blockIdx.z;
    src += b * sQK; dh += b * sQK; dl += b * sQK;
    const int i0 = blockIdx.x * 32;   // NPIX
    const int d0 = blockIdx.y * 32;   // DQK
    const int c = threadIdx.x & 31, r8 = threadIdx.x >> 5;

#pragma unroll
    for (int rr = 0; rr < 4; ++rr) {
        int row = rr * 8 + r8;        // d within tile
        t[row][c] = src[(long long)(d0 + row) * NPIX + i0 + c];
    }
    __syncthreads();
#pragma unroll
    for (int rr = 0; rr < 4; ++rr) {
        int row = rr * 8 + r8;        // i within tile
        float f = t[c][row];
        __nv_bfloat16 hi = __float2bfloat16(f);
        long long off = (long long)(i0 + row) * DQK + d0 + c;
        dh[off] = hi;
        dl[off] = __float2bfloat16(f - __bfloat162float(hi));
    }
}

// split v fp32 -> hi/lo bf16 (layout preserved)
__global__ __launch_bounds__(256) void vsplit_k(
    const float* __restrict__ v, __nv_bfloat16* __restrict__ vh,
    __nv_bfloat16* __restrict__ vl)
{
    int i = blockIdx.x * 256 + threadIdx.x;
    float f = v[i];
    __nv_bfloat16 hi = __float2bfloat16(f);
    vh[i] = hi;
    vl[i] = __float2bfloat16(f - __bfloat162float(hi));
}

// ---------------------------------------------------------------------------
// row softmax (4096) fp32 -> attn hi/lo bf16
// ---------------------------------------------------------------------------
__global__ __launch_bounds__(256) void softmax_k(
    const float* __restrict__ e, __nv_bfloat16* __restrict__ ah,
    __nv_bfloat16* __restrict__ al)
{
    const long long row = blockIdx.x;
    const float* p = e + row * (long long)NPIX;
    const int tid = threadIdx.x;

    float v[16];
#pragma unroll
    for (int k = 0; k < 16; k++) v[k] = p[tid + k * 256];

    float mx = -1e30f;
#pragma unroll
    for (int k = 0; k < 16; k++) mx = fmaxf(mx, v[k]);
#pragma unroll
    for (int o = 16; o > 0; o >>= 1) mx = fmaxf(mx, __shfl_xor_sync(0xffffffffu, mx, o));

    __shared__ float redm[8], reds[8];
    if ((tid & 31) == 0) redm[tid >> 5] = mx;
    __syncthreads();
    mx = redm[0];
#pragma unroll
    for (int i = 1; i < 8; i++) mx = fmaxf(mx, redm[i]);

    float s = 0.f;
#pragma unroll
    for (int k = 0; k < 16; k++) { v[k] = __expf(v[k] - mx); s += v[k]; }
#pragma unroll
    for (int o = 16; o > 0; o >>= 1) s += __shfl_xor_sync(0xffffffffu, s, o);
    if ((tid & 31) == 0) reds[tid >> 5] = s;
    __syncthreads();
    s = 0.f;
#pragma unroll
    for (int i = 0; i < 8; i++) s += reds[i];

    const float inv = 1.f / s;
    __nv_bfloat16* ph = ah + row * (long long)NPIX;
    __nv_bfloat16* pl = al + row * (long long)NPIX;
#pragma unroll
    for (int k = 0; k < 16; k++) {
        float a = v[k] * inv;
        __nv_bfloat16 hi = __float2bfloat16(a);
        ph[tid + k * 256] = hi;
        pl[tid + k * 256] = __float2bfloat16(a - __bfloat162float(hi));
    }
}

// ---------------------------------------------------------------------------
extern "C" void kernel_launch(void* const* d_in, const int* in_sizes, int n_in,
                              void* d_out, int out_size)
{
    const float* x     = (const float*)d_in[0];
    const float* dep   = (const float*)d_in[1];
    const float* wq    = (const float*)d_in[2];
    const float* bq    = (const float*)d_in[3];
    const float* wqd   = (const float*)d_in[4];
    const float* bqd   = (const float*)d_in[5];
    const float* wk    = (const float*)d_in[6];
    const float* bk    = (const float*)d_in[7];
    const float* wkd   = (const float*)d_in[8];
    const float* bkd   = (const float*)d_in[9];
    const float* wv    = (const float*)d_in[10];
    const float* bv    = (const float*)d_in[11];
    const float* gamma = (const float*)d_in[12];
    float* out = (float*)d_out;

    float *qp, *kp, *vp, *ep;
    __nv_bfloat16 *qh, *ql, *kh, *kl, *ahp, *alp, *vhp, *vlp;
    cudaGetSymbolAddress((void**)&qp, g_q);
    cudaGetSymbolAddress((void**)&kp, g_k);
    cudaGetSymbolAddress((void**)&vp, g_v);
    cudaGetSymbolAddress((void**)&ep, g_e);
    cudaGetSymbolAddress((void**)&qh, g_qh);
    cudaGetSymbolAddress((void**)&ql, g_ql);
    cudaGetSymbolAddress((void**)&kh, g_kh);
    cudaGetSymbolAddress((void**)&kl, g_kl);
    cudaGetSymbolAddress((void**)&ahp, g_ah);
    cudaGetSymbolAddress((void**)&alp, g_al);
    cudaGetSymbolAddress((void**)&vhp, g_vh);
    cudaGetSymbolAddress((void**)&vlp, g_vl);

    const long long sIn = (long long)CCH * NPIX;
    const long long sQK = (long long)DQK * NPIX;
    const long long sE  = (long long)NPIX * NPIX;

    dim3 blk(256);

    // ---- projections (fp32) ----
    {
        dim3 gq(NPIX / 64, 1, BATCH);
        gemm_k<64, 64, 16, 4, 4><<<gq, blk>>>(
            wq, x, qp, CCH, CCH, NPIX, NPIX, 0, sIn, sQK, bq);
        gemm_k<64, 64, 16, 4, 4><<<gq, blk>>>(
            wqd, dep, qp + (long long)CQ * NPIX, CCH, CCH, NPIX, NPIX, 0, sIn, sQK, bqd);
        gemm_k<64, 64, 16, 4, 4><<<gq, blk>>>(
            wk, x, kp, CCH, CCH, NPIX, NPIX, 0, sIn, sQK, bk);
        gemm_k<64, 64, 16, 4, 4><<<gq, blk>>>(
            wkd, dep, kp + (long long)CQ * NPIX, CCH, CCH, NPIX, NPIX, 0, sIn, sQK, bkd);
        dim3 gv(NPIX / 128, CCH / 64, BATCH);
        gemm_k<64, 128, 16, 4, 8><<<gv, blk>>>(
            wv, x, vp, CCH, CCH, NPIX, NPIX, 0, sIn, sIn, bv);
    }

    // ---- splits ----
    {
        dim3 gt(NPIX / 32, DQK / 32, BATCH);
        tsplit_k<<<gt, blk>>>(qp, qh, ql);
        tsplit_k<<<gt, blk>>>(kp, kh, kl);
        vsplit_k<<<BATCH * CCH * NPIX / 256, blk>>>(vp, vhp, vlp);
    }

    // ---- energy: bf16x3 HMMA, K=128 ----
    {
        dim3 ge(NPIX / 128, NPIX / 128, BATCH);
        mma_gemm<0><<<ge, blk, MMASMEM>>>(
            qh, ql, kh, kl, ep, DQK, sQK, sQK, sE, nullptr, nullptr);
    }

    // ---- softmax -> attn hi/lo bf16 ----
    softmax_k<<<BATCH * NPIX, blk>>>(ep, ahp, alp);

    // ---- out: bf16x3 HMMA, K=4096, epilogue gamma*acc + x ----
    {
        dim3 go(CCH / 128, NPIX / 128, BATCH);
        mma_gemm<2><<<go, blk, MMASMEM>>>(
            vhp, vlp, ahp, alp, out, NPIX, sIn, sE, sIn, x, gamma);
    }
}

// round 10
// speedup vs baseline: 1.9454x; 1.0596x over previous
#include <cuda_runtime.h>
#include <cuda_bf16.h>
#include <cstdint>

// PAM_Module_Dep attention. B=4, C=512, N=4096, D=128.
// R10 == R6 (audited 4x, unchanged; R6-R9 never ran - broker timeouts).
// cp.async 4-stage pipeline in HMMA GEMMs; q/k projections fused into one
// launch; v hi/lo split fused into v-projection epilogue.
// energy + out GEMMs: bf16 split-precision (3 passes, fp32 accum) ~1e-5 acc.

#define BATCH 4
#define CCH   512
#define NPIX  4096
#define DQK   128
#define CQ    64

// ---- device-global scratch (allocation-guard-safe) ----
__device__ float g_q[BATCH * DQK * NPIX];                    // q [b][d][i]
__device__ float g_k[BATCH * DQK * NPIX];
__device__ float g_e[(size_t)BATCH * NPIX * NPIX];           // energy fp32
__device__ __nv_bfloat16 g_qh[BATCH * NPIX * DQK];           // q^T hi [b][i][d]
__device__ __nv_bfloat16 g_ql[BATCH * NPIX * DQK];
__device__ __nv_bfloat16 g_kh[BATCH * NPIX * DQK];
__device__ __nv_bfloat16 g_kl[BATCH * NPIX * DQK];
__device__ __nv_bfloat16 g_ah[(size_t)BATCH * NPIX * NPIX];  // attn hi [b][i][j]
__device__ __nv_bfloat16 g_al[(size_t)BATCH * NPIX * NPIX];
__device__ __nv_bfloat16 g_vh[BATCH * CCH * NPIX];           // v hi [b][c][j]
__device__ __nv_bfloat16 g_vl[BATCH * CCH * NPIX];

__device__ __forceinline__ uint32_t smem_u32(const void* p) {
    uint32_t a;
    asm("{ .reg .u64 t; cvta.to.shared.u64 t, %1; cvt.u32.u64 %0, t; }"
        : "=r"(a) : "l"(p));
    return a;
}
#define LDSM4(r0, r1, r2, r3, addr)                                           \
    asm volatile("ldmatrix.sync.aligned.m8n8.x4.shared.b16 {%0,%1,%2,%3}, [%4];" \
                 : "=r"(r0), "=r"(r1), "=r"(r2), "=r"(r3) : "r"(addr))
#define MMA16816(d, a, b0, b1)                                                \
    asm volatile("mma.sync.aligned.m16n8k16.row.col.f32.bf16.bf16.f32 "       \
                 "{%0,%1,%2,%3}, {%4,%5,%6,%7}, {%8,%9}, {%0,%1,%2,%3};"      \
                 : "+f"((d)[0]), "+f"((d)[1]), "+f"((d)[2]), "+f"((d)[3])     \
                 : "r"((a)[0]), "r"((a)[1]), "r"((a)[2]), "r"((a)[3]),        \
                   "r"(b0), "r"(b1))
#define CP_ASYNC16(dst, src)                                                  \
    asm volatile("cp.async.cg.shared.global [%0], [%1], 16;"                  \
                 :: "r"(dst), "l"(src) : "memory")
#define CP_COMMIT() asm volatile("cp.async.commit_group;" ::: "memory")
#define CP_WAIT(n)  asm volatile("cp.async.wait_group %0;" :: "n"(n) : "memory")

// ============================================================================
// bf16 split-precision GEMM via mma.sync + cp.async 4-stage pipeline.
//   C[m,n] = sum over passes {(Ah,Bh),(Al,Bh),(Ah,Bl)} of sum_k A[m,k]*B[n,k]
// A: M x K row-major bf16; B: N x K row-major bf16 (K contiguous, 32B aligned).
// CTA 128x128, 8 warps (4 M x 2 N), warp tile 32x64, K-stage 32.
// EPI: 0 = plain fp32 store; 2 = gamma*acc + X.
// ============================================================================
#define STR 40                      // smem row stride in halves (80 B)
#define STAGE_B 10240               // 128 rows * 80 B
#define NSTG 4
#define MMASMEM (NSTG * 2 * STAGE_B)   // 81920 B

template <int EPI>
__global__ __launch_bounds__(256, 2) void mma_gemm(
    const __nv_bfloat16* __restrict__ Ah, const __nv_bfloat16* __restrict__ Al,
    const __nv_bfloat16* __restrict__ Bh, const __nv_bfloat16* __restrict__ Bl,
    float* __restrict__ C, int Ktot,
    long long sA, long long sB, long long sC,
    const float* __restrict__ X, const float* __restrict__ gam)
{
    extern __shared__ char smem[];
    const uint32_t sb = smem_u32(smem);
    const int tid = threadIdx.x, wid = tid >> 5, lane = tid & 31;
    const int wm = wid & 3, wn = wid >> 2;
    const int b = blockIdx.z;
    const int m0 = blockIdx.x * 128;
    const int n0 = blockIdx.y * 128;

    Ah += (long long)b * sA; Al += (long long)b * sA;
    Bh += (long long)b * sB; Bl += (long long)b * sB;
    C  += (long long)b * sC;

    const __nv_bfloat16* PA[3] = {Ah, Al, Ah};
    const __nv_bfloat16* PB[3] = {Bh, Bh, Bl};
    const int spp = Ktot / 32;          // stages per pass
    const int T = 3 * spp;

    const int lr0 = tid >> 2;           // row for chunk 0 (0..63)
    const int lu  = tid & 3;            // 16B chunk within 64B row

    auto issue = [&](int t) {
        const int pass = t / spp;
        const int kg = (t % spp) * 32;
        const uint32_t sa = sb + (uint32_t)(t & (NSTG - 1)) * (2 * STAGE_B);
        const uint32_t sbb = sa + STAGE_B;
        const __nv_bfloat16* A = PA[pass];
        const __nv_bfloat16* B = PB[pass];
#pragma unroll
        for (int it = 0; it < 2; ++it) {
            int r = lr0 + it * 64;
            CP_ASYNC16(sa + r * 80 + lu * 16,
                       A + (long long)(m0 + r) * Ktot + kg + lu * 8);
            CP_ASYNC16(sbb + r * 80 + lu * 16,
                       B + (long long)(n0 + r) * Ktot + kg + lu * 8);
        }
        CP_COMMIT();
    };

    float acc[2][8][4];
#pragma unroll
    for (int i = 0; i < 2; i++)
#pragma unroll
        for (int j = 0; j < 8; j++)
#pragma unroll
            for (int r = 0; r < 4; r++) acc[i][j][r] = 0.f;

    issue(0); issue(1); issue(2);       // T >= 12 always

    const int lrow = lane & 15;         // ldmatrix row within 16
    const int lcol = (lane >> 4) * 8;   // halves offset within k16

    for (int t = 0; t < T; ++t) {
        const int rem = T - 1 - t;
        if (rem >= 2)      CP_WAIT(2);
        else if (rem == 1) CP_WAIT(1);
        else               CP_WAIT(0);
        __syncthreads();
        if (t + 3 < T) issue(t + 3);

        const uint32_t baseA = sb + (uint32_t)(t & (NSTG - 1)) * (2 * STAGE_B);
        const uint32_t baseB = baseA + STAGE_B;
#pragma unroll
        for (int s = 0; s < 2; ++s) {
            uint32_t a[2][4], bf[4][4];
#pragma unroll
            for (int mt = 0; mt < 2; ++mt) {
                uint32_t ad = baseA +
                    ((wm * 32 + mt * 16 + lrow) * STR + s * 16 + lcol) * 2;
                LDSM4(a[mt][0], a[mt][1], a[mt][2], a[mt][3], ad);
            }
#pragma unroll
            for (int p = 0; p < 4; ++p) {
                uint32_t bd = baseB +
                    ((wn * 64 + p * 16 + lrow) * STR + s * 16 + lcol) * 2;
                LDSM4(bf[p][0], bf[p][1], bf[p][2], bf[p][3], bd);
            }
#pragma unroll
            for (int mt = 0; mt < 2; ++mt)
#pragma unroll
                for (int p = 0; p < 4; ++p) {
                    MMA16816(acc[mt][2 * p + 0], a[mt], bf[p][0], bf[p][2]);
                    MMA16816(acc[mt][2 * p + 1], a[mt], bf[p][1], bf[p][3]);
                }
        }
    }

    // epilogue: D frag (g=lane/4, c=lane%4): d0,d1 @ (g, 2c..), d2,d3 @ (g+8)
    const float g = (EPI == 2) ? gam[0] : 0.f;
    const float* Xb = (EPI == 2) ? X + (long long)b * sC : nullptr;
#pragma unroll
    for (int mt = 0; mt < 2; ++mt)
#pragma unroll
        for (int nt = 0; nt < 8; ++nt) {
            int row0 = m0 + wm * 32 + mt * 16 + (lane >> 2);
            int col  = n0 + wn * 64 + nt * 8 + (lane & 3) * 2;
#pragma unroll
            for (int h = 0; h < 2; ++h) {
                long long off = (long long)(row0 + h * 8) * NPIX + col;
                float2 v = make_float2(acc[mt][nt][2 * h], acc[mt][nt][2 * h + 1]);
                if (EPI == 2) {
                    float2 xx = *reinterpret_cast<const float2*>(Xb + off);
                    v.x = fmaf(g, v.x, xx.x);
                    v.y = fmaf(g, v.y, xx.y);
                }
                *reinterpret_cast<float2*>(C + off) = v;
            }
        }
}

// ============================================================================
// fp32 tiled GEMM (double-buffered) — v projection (EPI=3: bf16 hi/lo out).
// ============================================================================
template <int BM, int BN, int BK, int TM, int TN, int EPI>
__global__ __launch_bounds__(256, 2) void gemm_k(
    const float* __restrict__ A, const float* __restrict__ B,
    float* __restrict__ C,
    int K, int lda, int ldb, int ldc,
    long long sA, long long sB, long long sC,
    const float* __restrict__ bias,
    __nv_bfloat16* __restrict__ Ch, __nv_bfloat16* __restrict__ Cl)
{
    constexpr int NT = 256;
    static_assert((BM / TM) * (BN / TN) == NT, "tiling");
    constexpr int ALD = BM * BK / 4 / NT;
    constexpr int BLD = BN * BK / 4 / NT;

    __shared__ float As[2][BK][BM + 4];
    __shared__ float Bs[2][BK][BN + 4];

    const int b = blockIdx.z;
    A += (long long)b * sA;
    B += (long long)b * sB;
    if (EPI == 1) C += (long long)b * sC;
    if (EPI == 3) { Ch += (long long)b * sC; Cl += (long long)b * sC; }

    const int m0 = blockIdx.y * BM;
    const int n0 = blockIdx.x * BN;
    const int tid = threadIdx.x;
    const int tx = tid % (BN / TN);
    const int ty = tid / (BN / TN);

    float4 ra[ALD], rb[BLD];

    auto loadA = [&](int k0) {   // A row-major [M][K]
#pragma unroll
        for (int it = 0; it < ALD; ++it) {
            int idx = tid + it * NT;
            int r = idx / (BK / 4), c = idx % (BK / 4);
            ra[it] = *reinterpret_cast<const float4*>(
                &A[(long long)(m0 + r) * lda + k0 + c * 4]);
        }
    };
    auto stashA = [&](int buf) {
#pragma unroll
        for (int it = 0; it < ALD; ++it) {
            int idx = tid + it * NT;
            int r = idx / (BK / 4), c = idx % (BK / 4);
            As[buf][c * 4 + 0][r] = ra[it].x;
            As[buf][c * 4 + 1][r] = ra[it].y;
            As[buf][c * 4 + 2][r] = ra[it].z;
            As[buf][c * 4 + 3][r] = ra[it].w;
        }
    };
    auto loadB = [&](int k0) {   // B K-major [K][N]
#pragma unroll
        for (int it = 0; it < BLD; ++it) {
            int idx = tid + it * NT;
            int r = idx / (BN / 4), c = idx % (BN / 4);
            rb[it] = *reinterpret_cast<const float4*>(
                &B[(long long)(k0 + r) * ldb + n0 + c * 4]);
        }
    };
    auto stashB = [&](int buf) {
#pragma unroll
        for (int it = 0; it < BLD; ++it) {
            int idx = tid + it * NT;
            int r = idx / (BN / 4), c = idx % (BN / 4);
            *reinterpret_cast<float4*>(&Bs[buf][r][c * 4]) = rb[it];
        }
    };

    float acc[TM][TN];
#pragma unroll
    for (int i = 0; i < TM; i++)
#pragma unroll
        for (int j = 0; j < TN; j++) acc[i][j] = 0.f;

    loadA(0); loadB(0);
    stashA(0); stashB(0);
    __syncthreads();

    const int nTiles = K / BK;
    for (int t = 0; t < nTiles; ++t) {
        const int cur = t & 1;
        const bool more = (t + 1 < nTiles);
        if (more) { loadA((t + 1) * BK); loadB((t + 1) * BK); }

#pragma unroll
        for (int kk = 0; kk < BK; kk++) {
            float a[TM], bb[TN];
#pragma unroll
            for (int i = 0; i < TM; i++) a[i] = As[cur][kk][ty * TM + i];
#pragma unroll
            for (int j = 0; j < TN; j++) bb[j] = Bs[cur][kk][tx * TN + j];
#pragma unroll
            for (int i = 0; i < TM; i++)
#pragma unroll
                for (int j = 0; j < TN; j++)
                    acc[i][j] = fmaf(a[i], bb[j], acc[i][j]);
        }
        if (more) {
            stashA(cur ^ 1); stashB(cur ^ 1);
            __syncthreads();
        }
    }

#pragma unroll
    for (int i = 0; i < TM; i++) {
        int m = m0 + ty * TM + i;
        float bi = bias[m];
#pragma unroll
        for (int j = 0; j < TN; j++) {
            int n = n0 + tx * TN + j;
            long long off = (long long)m * ldc + n;
            float f = acc[i][j] + bi;
            if (EPI == 1) {
                C[off] = f;
            } else {
                __nv_bfloat16 hi = __float2bfloat16(f);
                Ch[off] = hi;
                Cl[off] = __float2bfloat16(f - __bfloat162float(hi));
            }
        }
    }
}

// ============================================================================
// Combined q/k projections: 4 GEMMs (wq,wqd,wk,wkd) in one launch.
// Each: C[m,n] = sum_c W[m,c]*src[c,n] + bias[m], M=64, N=4096, K=512.
// blockIdx.y selects which projection. Tile 64x64, TM=TN=4.
// ============================================================================
struct QKTab {
    const float* W[4];
    const float* S[4];
    const float* bias[4];
    float* D[4];
};

__global__ __launch_bounds__(256, 2) void gemm_qk(QKTab tab)
{
    __shared__ float As[2][16][68];
    __shared__ float Bs[2][16][68];

    const int b = blockIdx.z, sel = blockIdx.y;
    const float* A = tab.W[sel];
    const float* B = tab.S[sel] + (long long)b * ((long long)CCH * NPIX);
    float* C = tab.D[sel] + (long long)b * ((long long)DQK * NPIX);
    const float* bias = tab.bias[sel];

    const int n0 = blockIdx.x * 64;
    const int tid = threadIdx.x;
    const int tx = tid % 16;
    const int ty = tid / 16;

    float4 ra, rb;
    auto loadA = [&](int k0) {          // W row-major [64][512]
        int r = tid / 4, c = tid % 4;
        ra = *reinterpret_cast<const float4*>(&A[(long long)r * CCH + k0 + c * 4]);
    };
    auto stashA = [&](int buf) {
        int r = tid / 4, c = tid % 4;
        As[buf][c * 4 + 0][r] = ra.x;
        As[buf][c * 4 + 1][r] = ra.y;
        As[buf][c * 4 + 2][r] = ra.z;
        As[buf][c * 4 + 3][r] = ra.w;
    };
    auto loadB = [&](int k0) {          // src K-major [512][4096]
        int r = tid / 16, c = tid % 16;
        rb = *reinterpret_cast<const float4*>(&B[(long long)(k0 + r) * NPIX + n0 + c * 4]);
    };
    auto stashB = [&](int buf) {
        int r = tid / 16, c = tid % 16;
        *reinterpret_cast<float4*>(&Bs[buf][r][c * 4]) = rb;
    };

    float acc[4][4];
#pragma unroll
    for (int i = 0; i < 4; i++)
#pragma unroll
        for (int j = 0; j < 4; j++) acc[i][j] = 0.f;

    loadA(0); loadB(0);
    stashA(0); stashB(0);
    __syncthreads();

    for (int t = 0; t < CCH / 16; ++t) {
        const int cur = t & 1;
        const bool more = (t + 1 < CCH / 16);
        if (more) { loadA((t + 1) * 16); loadB((t + 1) * 16); }

#pragma unroll
        for (int kk = 0; kk < 16; kk++) {
            float a[4], bb[4];
#pragma unroll
            for (int i = 0; i < 4; i++) a[i] = As[cur][kk][ty * 4 + i];
#pragma unroll
            for (int j = 0; j < 4; j++) bb[j] = Bs[cur][kk][tx * 4 + j];
#pragma unroll
            for (int i = 0; i < 4; i++)
#pragma unroll
                for (int j = 0; j < 4; j++)
                    acc[i][j] = fmaf(a[i], bb[j], acc[i][j]);
        }
        if (more) {
            stashA(cur ^ 1); stashB(cur ^ 1);
            __syncthreads();
        }
    }

#pragma unroll
    for (int i = 0; i < 4; i++) {
        int m = ty * 4 + i;
        float bi = bias[m];
#pragma unroll
        for (int j = 0; j < 4; j++) {
            int n = n0 + tx * 4 + j;
            C[(long long)m * NPIX + n] = acc[i][j] + bi;
        }
    }
}

// ---------------------------------------------------------------------------
// transpose + hi/lo split: src fp32 [D][N] -> dh/dl bf16 [N][D]  (per batch)
// ---------------------------------------------------------------------------
__global__ __launch_bounds__(256) void tsplit_k(
    const float* __restrict__ src, __nv_bfloat16* __restrict__ dh,
    __nv_bfloat16* __restrict__ dl)
{
    __shared__ float t[32][33];
    const long long sQK = (long long)DQK * NPIX;
    const int b = blockIdx.z;
    src += b * sQK; dh += b * sQK; dl += b * sQK;
    const int i0 = blockIdx.x * 32;   // NPIX
    const int d0 = blockIdx.y * 32;   // DQK
    const int c = threadIdx.x & 31, r8 = threadIdx.x >> 5;

#pragma unroll
    for (int rr = 0; rr < 4; ++rr) {
        int row = rr * 8 + r8;
        t[row][c] = src[(long long)(d0 + row) * NPIX + i0 + c];
    }
    __syncthreads();
#pragma unroll
    for (int rr = 0; rr < 4; ++rr) {
        int row = rr * 8 + r8;
        float f = t[c][row];
        __nv_bfloat16 hi = __float2bfloat16(f);
        long long off = (long long)(i0 + row) * DQK + d0 + c;
        dh[off] = hi;
        dl[off] = __float2bfloat16(f - __bfloat162float(hi));
    }
}

// ---------------------------------------------------------------------------
// row softmax (4096) fp32 -> attn hi/lo bf16
// ---------------------------------------------------------------------------
__global__ __launch_bounds__(256) void softmax_k(
    const float* __restrict__ e, __nv_bfloat16* __restrict__ ah,
    __nv_bfloat16* __restrict__ al)
{
    const long long row = blockIdx.x;
    const float* p = e + row * (long long)NPIX;
    const int tid = threadIdx.x;

    float v[16];
#pragma unroll
    for (int k = 0; k < 16; k++) v[k] = p[tid + k * 256];

    float mx = -1e30f;
#pragma unroll
    for (int k = 0; k < 16; k++) mx = fmaxf(mx, v[k]);
#pragma unroll
    for (int o = 16; o > 0; o >>= 1) mx = fmaxf(mx, __shfl_xor_sync(0xffffffffu, mx, o));

    __shared__ float redm[8], reds[8];
    if ((tid & 31) == 0) redm[tid >> 5] = mx;
    __syncthreads();
    mx = redm[0];
#pragma unroll
    for (int i = 1; i < 8; i++) mx = fmaxf(mx, redm[i]);

    float s = 0.f;
#pragma unroll
    for (int k = 0; k < 16; k++) { v[k] = __expf(v[k] - mx); s += v[k]; }
#pragma unroll
    for (int o = 16; o > 0; o >>= 1) s += __shfl_xor_sync(0xffffffffu, s, o);
    if ((tid & 31) == 0) reds[tid >> 5] = s;
    __syncthreads();
    s = 0.f;
#pragma unroll
    for (int i = 0; i < 8; i++) s += reds[i];

    const float inv = 1.f / s;
    __nv_bfloat16* ph = ah + row * (long long)NPIX;
    __nv_bfloat16* pl = al + row * (long long)NPIX;
#pragma unroll
    for (int k = 0; k < 16; k++) {
        float a = v[k] * inv;
        __nv_bfloat16 hi = __float2bfloat16(a);
        ph[tid + k * 256] = hi;
        pl[tid + k * 256] = __float2bfloat16(a - __bfloat162float(hi));
    }
}

// ---------------------------------------------------------------------------
extern "C" void kernel_launch(void* const* d_in, const int* in_sizes, int n_in,
                              void* d_out, int out_size)
{
    const float* x     = (const float*)d_in[0];
    const float* dep   = (const float*)d_in[1];
    const float* wq    = (const float*)d_in[2];
    const float* bq    = (const float*)d_in[3];
    const float* wqd   = (const float*)d_in[4];
    const float* bqd   = (const float*)d_in[5];
    const float* wk    = (const float*)d_in[6];
    const float* bk    = (const float*)d_in[7];
    const float* wkd   = (const float*)d_in[8];
    const float* bkd   = (const float*)d_in[9];
    const float* wv    = (const float*)d_in[10];
    const float* bv    = (const float*)d_in[11];
    const float* gamma = (const float*)d_in[12];
    float* out = (float*)d_out;

    float *qp, *kp, *ep;
    __nv_bfloat16 *qh, *ql, *kh, *kl, *ahp, *alp, *vhp, *vlp;
    cudaGetSymbolAddress((void**)&qp, g_q);
    cudaGetSymbolAddress((void**)&kp, g_k);
    cudaGetSymbolAddress((void**)&ep, g_e);
    cudaGetSymbolAddress((void**)&qh, g_qh);
    cudaGetSymbolAddress((void**)&ql, g_ql);
    cudaGetSymbolAddress((void**)&kh, g_kh);
    cudaGetSymbolAddress((void**)&kl, g_kl);
    cudaGetSymbolAddress((void**)&ahp, g_ah);
    cudaGetSymbolAddress((void**)&alp, g_al);
    cudaGetSymbolAddress((void**)&vhp, g_vh);
    cudaGetSymbolAddress((void**)&vlp, g_vl);

    const long long sIn = (long long)CCH * NPIX;
    const long long sQK = (long long)DQK * NPIX;
    const long long sE  = (long long)NPIX * NPIX;

    cudaFuncSetAttribute(mma_gemm<0>, cudaFuncAttributeMaxDynamicSharedMemorySize,
                         MMASMEM);
    cudaFuncSetAttribute(mma_gemm<2>, cudaFuncAttributeMaxDynamicSharedMemorySize,
                         MMASMEM);

    dim3 blk(256);

    // ---- q/k projections: one launch, 4 GEMMs ----
    {
        QKTab tab;
        tab.W[0] = wq;  tab.S[0] = x;   tab.bias[0] = bq;  tab.D[0] = qp;
        tab.W[1] = wqd; tab.S[1] = dep; tab.bias[1] = bqd; tab.D[1] = qp + (long long)CQ * NPIX;
        tab.W[2] = wk;  tab.S[2] = x;   tab.bias[2] = bk;  tab.D[2] = kp;
        tab.W[3] = wkd; tab.S[3] = dep; tab.bias[3] = bkd; tab.D[3] = kp + (long long)CQ * NPIX;
        dim3 gq(NPIX / 64, 4, BATCH);
        gemm_qk<<<gq, blk>>>(tab);
    }

    // ---- v projection: fp32 GEMM, bf16 hi/lo epilogue ----
    {
        dim3 gv(NPIX / 128, CCH / 64, BATCH);
        gemm_k<64, 128, 16, 4, 8, 3><<<gv, blk>>>(
            wv, x, nullptr, CCH, CCH, NPIX, NPIX, 0, sIn, sIn, bv, vhp, vlp);
    }

    // ---- q/k transpose + split ----
    {
        dim3 gt(NPIX / 32, DQK / 32, BATCH);
        tsplit_k<<<gt, blk>>>(qp, qh, ql);
        tsplit_k<<<gt, blk>>>(kp, kh, kl);
    }

    // ---- energy: bf16x3 HMMA, K=128 ----
    {
        dim3 ge(NPIX / 128, NPIX / 128, BATCH);
        mma_gemm<0><<<ge, blk, MMASMEM>>>(
            qh, ql, kh, kl, ep, DQK, sQK, sQK, sE, nullptr, nullptr);
    }

    // ---- softmax -> attn hi/lo bf16 ----
    softmax_k<<<BATCH * NPIX, blk>>>(ep, ahp, alp);

    // ---- out: bf16x3 HMMA, K=4096, epilogue gamma*acc + x ----
    {
        dim3 go(CCH / 128, NPIX / 128, BATCH);
        mma_gemm<2><<<go, blk, MMASMEM>>>(
            vhp, vlp, ahp, alp, out, NPIX, sIn, sE, sIn, x, gamma);
    }
}

// round 12
// speedup vs baseline: 1.9517x; 1.0032x over previous
#include <cuda_runtime.h>
#include <cuda_bf16.h>
#include <cstdint>

// PAM_Module_Dep attention. B=4, C=512, N=4096, D=128.
// R12 == R11 (audited, unchanged; R11 never ran - broker timeout).
// mma_gemm v3: 3 split-precision passes interleaved INSIDE each K-stage
// (tiles Ah,Al,Bh,Bl loaded once per stage, 3 MMA combos into one
// accumulator). Gmem streams 6->4, stages/barriers /3, LDSM per MMA x2/3.

#define BATCH 4
#define CCH   512
#define NPIX  4096
#define DQK   128
#define CQ    64

// ---- device-global scratch (allocation-guard-safe) ----
__device__ float g_q[BATCH * DQK * NPIX];                    // q [b][d][i]
__device__ float g_k[BATCH * DQK * NPIX];
__device__ float g_e[(size_t)BATCH * NPIX * NPIX];           // energy fp32
__device__ __nv_bfloat16 g_qh[BATCH * NPIX * DQK];           // q^T hi [b][i][d]
__device__ __nv_bfloat16 g_ql[BATCH * NPIX * DQK];
__device__ __nv_bfloat16 g_kh[BATCH * NPIX * DQK];
__device__ __nv_bfloat16 g_kl[BATCH * NPIX * DQK];
__device__ __nv_bfloat16 g_ah[(size_t)BATCH * NPIX * NPIX];  // attn hi [b][i][j]
__device__ __nv_bfloat16 g_al[(size_t)BATCH * NPIX * NPIX];
__device__ __nv_bfloat16 g_vh[BATCH * CCH * NPIX];           // v hi [b][c][j]
__device__ __nv_bfloat16 g_vl[BATCH * CCH * NPIX];

__device__ __forceinline__ uint32_t smem_u32(const void* p) {
    uint32_t a;
    asm("{ .reg .u64 t; cvta.to.shared.u64 t, %1; cvt.u32.u64 %0, t; }"
        : "=r"(a) : "l"(p));
    return a;
}
#define LDSM4(r0, r1, r2, r3, addr)                                           \
    asm volatile("ldmatrix.sync.aligned.m8n8.x4.shared.b16 {%0,%1,%2,%3}, [%4];" \
                 : "=r"(r0), "=r"(r1), "=r"(r2), "=r"(r3) : "r"(addr))
#define MMA16816(d, a, b0, b1)                                                \
    asm volatile("mma.sync.aligned.m16n8k16.row.col.f32.bf16.bf16.f32 "       \
                 "{%0,%1,%2,%3}, {%4,%5,%6,%7}, {%8,%9}, {%0,%1,%2,%3};"      \
                 : "+f"((d)[0]), "+f"((d)[1]), "+f"((d)[2]), "+f"((d)[3])     \
                 : "r"((a)[0]), "r"((a)[1]), "r"((a)[2]), "r"((a)[3]),        \
                   "r"(b0), "r"(b1))
#define CP_ASYNC16(dst, src)                                                  \
    asm volatile("cp.async.cg.shared.global [%0], [%1], 16;"                  \
                 :: "r"(dst), "l"(src) : "memory")
#define CP_COMMIT() asm volatile("cp.async.commit_group;" ::: "memory")
#define CP_WAIT(n)  asm volatile("cp.async.wait_group %0;" :: "n"(n) : "memory")

// ============================================================================
// bf16 split-precision GEMM via mma.sync, interleaved passes + cp.async.
//   C[m,n] = sum_k Ah*Bh + Al*Bh + Ah*Bl   (all into one fp32 accumulator)
// A: M x K row-major bf16; B: N x K row-major bf16 (K contiguous).
// CTA 128x128, 8 warps (4 M x 2 N), warp tile 32x64, K-stage 32.
// Stage holds 4 tiles (Ah,Al,Bh,Bl), NSTG=4 ring, prefetch distance 3.
// EPI: 0 = plain fp32 store; 2 = gamma*acc + X.
// ============================================================================
#define STR 40                      // smem row stride in halves (80 B)
#define STAGE_B 10240               // one tile: 128 rows * 80 B
#define TILE4   (4 * STAGE_B)       // Ah,Al,Bh,Bl per stage = 40960 B
#define NSTG 4
#define MMASMEM (NSTG * TILE4)      // 163840 B -> 1 CTA/SM

template <int EPI>
__global__ __launch_bounds__(256, 1) void mma_gemm(
    const __nv_bfloat16* __restrict__ Ah, const __nv_bfloat16* __restrict__ Al,
    const __nv_bfloat16* __restrict__ Bh, const __nv_bfloat16* __restrict__ Bl,
    float* __restrict__ C, int Ktot,
    long long sA, long long sB, long long sC,
    const float* __restrict__ X, const float* __restrict__ gam)
{
    extern __shared__ char smem[];
    const uint32_t sb = smem_u32(smem);
    const int tid = threadIdx.x, wid = tid >> 5, lane = tid & 31;
    const int wm = wid & 3, wn = wid >> 2;
    const int b = blockIdx.z;
    const int m0 = blockIdx.x * 128;
    const int n0 = blockIdx.y * 128;

    Ah += (long long)b * sA; Al += (long long)b * sA;
    Bh += (long long)b * sB; Bl += (long long)b * sB;
    C  += (long long)b * sC;

    const int T = Ktot / 32;            // K-stages (out: 128, energy: 4)

    const int lr0 = tid >> 2;           // row for chunk 0 (0..63)
    const int lu  = tid & 3;            // 16B chunk within 64B row

    auto issue = [&](int t) {
        const int kg = t * 32;
        const uint32_t base = sb + (uint32_t)(t & (NSTG - 1)) * TILE4;
#pragma unroll
        for (int it = 0; it < 2; ++it) {
            int r = lr0 + it * 64;
            long long offA = (long long)(m0 + r) * Ktot + kg + lu * 8;
            long long offB = (long long)(n0 + r) * Ktot + kg + lu * 8;
            uint32_t d = base + r * 80 + lu * 16;
            CP_ASYNC16(d,               Ah + offA);
            CP_ASYNC16(d + STAGE_B,     Al + offA);
            CP_ASYNC16(d + 2 * STAGE_B, Bh + offB);
            CP_ASYNC16(d + 3 * STAGE_B, Bl + offB);
        }
        CP_COMMIT();
    };

    float acc[2][8][4];
#pragma unroll
    for (int i = 0; i < 2; i++)
#pragma unroll
        for (int j = 0; j < 8; j++)
#pragma unroll
            for (int r = 0; r < 4; r++) acc[i][j][r] = 0.f;

    issue(0); issue(1); issue(2);       // T >= 4 always

    const int lrow = lane & 15;         // ldmatrix row within 16
    const int lcol = (lane >> 4) * 8;   // halves offset within k16

    for (int t = 0; t < T; ++t) {
        const int rem = T - 1 - t;
        if (rem >= 2)      CP_WAIT(2);
        else if (rem == 1) CP_WAIT(1);
        else               CP_WAIT(0);
        __syncthreads();
        if (t + 3 < T) issue(t + 3);

        const uint32_t base = sb + (uint32_t)(t & (NSTG - 1)) * TILE4;
#pragma unroll
        for (int s = 0; s < 2; ++s) {
            uint32_t aH[2][4], aL[2][4];
#pragma unroll
            for (int mt = 0; mt < 2; ++mt) {
                uint32_t ad = base +
                    ((wm * 32 + mt * 16 + lrow) * STR + s * 16 + lcol) * 2;
                LDSM4(aH[mt][0], aH[mt][1], aH[mt][2], aH[mt][3], ad);
                LDSM4(aL[mt][0], aL[mt][1], aL[mt][2], aL[mt][3], ad + STAGE_B);
            }
#pragma unroll
            for (int p = 0; p < 4; ++p) {
                uint32_t bh[4], bl[4];
                uint32_t bd = base + 2 * STAGE_B +
                    ((wn * 64 + p * 16 + lrow) * STR + s * 16 + lcol) * 2;
                LDSM4(bh[0], bh[1], bh[2], bh[3], bd);
                LDSM4(bl[0], bl[1], bl[2], bl[3], bd + STAGE_B);
#pragma unroll
                for (int mt = 0; mt < 2; ++mt) {
                    MMA16816(acc[mt][2 * p + 0], aH[mt], bh[0], bh[2]);
                    MMA16816(acc[mt][2 * p + 1], aH[mt], bh[1], bh[3]);
                    MMA16816(acc[mt][2 * p + 0], aL[mt], bh[0], bh[2]);
                    MMA16816(acc[mt][2 * p + 1], aL[mt], bh[1], bh[3]);
                    MMA16816(acc[mt][2 * p + 0], aH[mt], bl[0], bl[2]);
                    MMA16816(acc[mt][2 * p + 1], aH[mt], bl[1], bl[3]);
                }
            }
        }
    }

    // epilogue: D frag (g=lane/4, c=lane%4): d0,d1 @ (g, 2c..), d2,d3 @ (g+8)
    const float g = (EPI == 2) ? gam[0] : 0.f;
    const float* Xb = (EPI == 2) ? X + (long long)b * sC : nullptr;
#pragma unroll
    for (int mt = 0; mt < 2; ++mt)
#pragma unroll
        for (int nt = 0; nt < 8; ++nt) {
            int row0 = m0 + wm * 32 + mt * 16 + (lane >> 2);
            int col  = n0 + wn * 64 + nt * 8 + (lane & 3) * 2;
#pragma unroll
            for (int h = 0; h < 2; ++h) {
                long long off = (long long)(row0 + h * 8) * NPIX + col;
                float2 v = make_float2(acc[mt][nt][2 * h], acc[mt][nt][2 * h + 1]);
                if (EPI == 2) {
                    float2 xx = *reinterpret_cast<const float2*>(Xb + off);
                    v.x = fmaf(g, v.x, xx.x);
                    v.y = fmaf(g, v.y, xx.y);
                }
                *reinterpret_cast<float2*>(C + off) = v;
            }
        }
}

// ============================================================================
// fp32 tiled GEMM (double-buffered) — v projection (EPI=3: bf16 hi/lo out).
// ============================================================================
template <int BM, int BN, int BK, int TM, int TN, int EPI>
__global__ __launch_bounds__(256, 2) void gemm_k(
    const float* __restrict__ A, const float* __restrict__ B,
    float* __restrict__ C,
    int K, int lda, int ldb, int ldc,
    long long sA, long long sB, long long sC,
    const float* __restrict__ bias,
    __nv_bfloat16* __restrict__ Ch, __nv_bfloat16* __restrict__ Cl)
{
    constexpr int NT = 256;
    static_assert((BM / TM) * (BN / TN) == NT, "tiling");
    constexpr int ALD = BM * BK / 4 / NT;
    constexpr int BLD = BN * BK / 4 / NT;

    __shared__ float As[2][BK][BM + 4];
    __shared__ float Bs[2][BK][BN + 4];

    const int b = blockIdx.z;
    A += (long long)b * sA;
    B += (long long)b * sB;
    if (EPI == 1) C += (long long)b * sC;
    if (EPI == 3) { Ch += (long long)b * sC; Cl += (long long)b * sC; }

    const int m0 = blockIdx.y * BM;
    const int n0 = blockIdx.x * BN;
    const int tid = threadIdx.x;
    const int tx = tid % (BN / TN);
    const int ty = tid / (BN / TN);

    float4 ra[ALD], rb[BLD];

    auto loadA = [&](int k0) {   // A row-major [M][K]
#pragma unroll
        for (int it = 0; it < ALD; ++it) {
            int idx = tid + it * NT;
            int r = idx / (BK / 4), c = idx % (BK / 4);
            ra[it] = *reinterpret_cast<const float4*>(
                &A[(long long)(m0 + r) * lda + k0 + c * 4]);
        }
    };
    auto stashA = [&](int buf) {
#pragma unroll
        for (int it = 0; it < ALD; ++it) {
            int idx = tid + it * NT;
            int r = idx / (BK / 4), c = idx % (BK / 4);
            As[buf][c * 4 + 0][r] = ra[it].x;
            As[buf][c * 4 + 1][r] = ra[it].y;
            As[buf][c * 4 + 2][r] = ra[it].z;
            As[buf][c * 4 + 3][r] = ra[it].w;
        }
    };
    auto loadB = [&](int k0) {   // B K-major [K][N]
#pragma unroll
        for (int it = 0; it < BLD; ++it) {
            int idx = tid + it * NT;
            int r = idx / (BN / 4), c = idx % (BN / 4);
            rb[it] = *reinterpret_cast<const float4*>(
                &B[(long long)(k0 + r) * ldb + n0 + c * 4]);
        }
    };
    auto stashB = [&](int buf) {
#pragma unroll
        for (int it = 0; it < BLD; ++it) {
            int idx = tid + it * NT;
            int r = idx / (BN / 4), c = idx % (BN / 4);
            *reinterpret_cast<float4*>(&Bs[buf][r][c * 4]) = rb[it];
        }
    };

    float acc[TM][TN];
#pragma unroll
    for (int i = 0; i < TM; i++)
#pragma unroll
        for (int j = 0; j < TN; j++) acc[i][j] = 0.f;

    loadA(0); loadB(0);
    stashA(0); stashB(0);
    __syncthreads();

    const int nTiles = K / BK;
    for (int t = 0; t < nTiles; ++t) {
        const int cur = t & 1;
        const bool more = (t + 1 < nTiles);
        if (more) { loadA((t + 1) * BK); loadB((t + 1) * BK); }

#pragma unroll
        for (int kk = 0; kk < BK; kk++) {
            float a[TM], bb[TN];
#pragma unroll
            for (int i = 0; i < TM; i++) a[i] = As[cur][kk][ty * TM + i];
#pragma unroll
            for (int j = 0; j < TN; j++) bb[j] = Bs[cur][kk][tx * TN + j];
#pragma unroll
            for (int i = 0; i < TM; i++)
#pragma unroll
                for (int j = 0; j < TN; j++)
                    acc[i][j] = fmaf(a[i], bb[j], acc[i][j]);
        }
        if (more) {
            stashA(cur ^ 1); stashB(cur ^ 1);
            __syncthreads();
        }
    }

#pragma unroll
    for (int i = 0; i < TM; i++) {
        int m = m0 + ty * TM + i;
        float bi = bias[m];
#pragma unroll
        for (int j = 0; j < TN; j++) {
            int n = n0 + tx * TN + j;
            long long off = (long long)m * ldc + n;
            float f = acc[i][j] + bi;
            if (EPI == 1) {
                C[off] = f;
            } else {
                __nv_bfloat16 hi = __float2bfloat16(f);
                Ch[off] = hi;
                Cl[off] = __float2bfloat16(f - __bfloat162float(hi));
            }
        }
    }
}

// ============================================================================
// Combined q/k projections: 4 GEMMs (wq,wqd,wk,wkd) in one launch.
// ============================================================================
struct QKTab {
    const float* W[4];
    const float* S[4];
    const float* bias[4];
    float* D[4];
};

__global__ __launch_bounds__(256, 2) void gemm_qk(QKTab tab)
{
    __shared__ float As[2][16][68];
    __shared__ float Bs[2][16][68];

    const int b = blockIdx.z, sel = blockIdx.y;
    const float* A = tab.W[sel];
    const float* B = tab.S[sel] + (long long)b * ((long long)CCH * NPIX);
    float* C = tab.D[sel] + (long long)b * ((long long)DQK * NPIX);
    const float* bias = tab.bias[sel];

    const int n0 = blockIdx.x * 64;
    const int tid = threadIdx.x;
    const int tx = tid % 16;
    const int ty = tid / 16;

    float4 ra, rb;
    auto loadA = [&](int k0) {          // W row-major [64][512]
        int r = tid / 4, c = tid % 4;
        ra = *reinterpret_cast<const float4*>(&A[(long long)r * CCH + k0 + c * 4]);
    };
    auto stashA = [&](int buf) {
        int r = tid / 4, c = tid % 4;
        As[buf][c * 4 + 0][r] = ra.x;
        As[buf][c * 4 + 1][r] = ra.y;
        As[buf][c * 4 + 2][r] = ra.z;
        As[buf][c * 4 + 3][r] = ra.w;
    };
    auto loadB = [&](int k0) {          // src K-major [512][4096]
        int r = tid / 16, c = tid % 16;
        rb = *reinterpret_cast<const float4*>(&B[(long long)(k0 + r) * NPIX + n0 + c * 4]);
    };
    auto stashB = [&](int buf) {
        int r = tid / 16, c = tid % 16;
        *reinterpret_cast<float4*>(&Bs[buf][r][c * 4]) = rb;
    };

    float acc[4][4];
#pragma unroll
    for (int i = 0; i < 4; i++)
#pragma unroll
        for (int j = 0; j < 4; j++) acc[i][j] = 0.f;

    loadA(0); loadB(0);
    stashA(0); stashB(0);
    __syncthreads();

    for (int t = 0; t < CCH / 16; ++t) {
        const int cur = t & 1;
        const bool more = (t + 1 < CCH / 16);
        if (more) { loadA((t + 1) * 16); loadB((t + 1) * 16); }

#pragma unroll
        for (int kk = 0; kk < 16; kk++) {
            float a[4], bb[4];
#pragma unroll
            for (int i = 0; i < 4; i++) a[i] = As[cur][kk][ty * 4 + i];
#pragma unroll
            for (int j = 0; j < 4; j++) bb[j] = Bs[cur][kk][tx * 4 + j];
#pragma unroll
            for (int i = 0; i < 4; i++)
#pragma unroll
                for (int j = 0; j < 4; j++)
                    acc[i][j] = fmaf(a[i], bb[j], acc[i][j]);
        }
        if (more) {
            stashA(cur ^ 1); stashB(cur ^ 1);
            __syncthreads();
        }
    }

#pragma unroll
    for (int i = 0; i < 4; i++) {
        int m = ty * 4 + i;
        float bi = bias[m];
#pragma unroll
        for (int j = 0; j < 4; j++) {
            int n = n0 + tx * 4 + j;
            C[(long long)m * NPIX + n] = acc[i][j] + bi;
        }
    }
}

// ---------------------------------------------------------------------------
// transpose + hi/lo split: src fp32 [D][N] -> dh/dl bf16 [N][D]  (per batch)
// ---------------------------------------------------------------------------
__global__ __launch_bounds__(256) void tsplit_k(
    const float* __restrict__ src, __nv_bfloat16* __restrict__ dh,
    __nv_bfloat16* __restrict__ dl)
{
    __shared__ float t[32][33];
    const long long sQK = (long long)DQK * NPIX;
    const int b = blockIdx.z;
    src += b * sQK; dh += b * sQK; dl += b * sQK;
    const int i0 = blockIdx.x * 32;   // NPIX
    const int d0 = blockIdx.y * 32;   // DQK
    const int c = threadIdx.x & 31, r8 = threadIdx.x >> 5;

#pragma unroll
    for (int rr = 0; rr < 4; ++rr) {
        int row = rr * 8 + r8;
        t[row][c] = src[(long long)(d0 + row) * NPIX + i0 + c];
    }
    __syncthreads();
#pragma unroll
    for (int rr = 0; rr < 4; ++rr) {
        int row = rr * 8 + r8;
        float f = t[c][row];
        __nv_bfloat16 hi = __float2bfloat16(f);
        long long off = (long long)(i0 + row) * DQK + d0 + c;
        dh[off] = hi;
        dl[off] = __float2bfloat16(f - __bfloat162float(hi));
    }
}

// ---------------------------------------------------------------------------
// row softmax (4096) fp32 -> attn hi/lo bf16
// ---------------------------------------------------------------------------
__global__ __launch_bounds__(256) void softmax_k(
    const float* __restrict__ e, __nv_bfloat16* __restrict__ ah,
    __nv_bfloat16* __restrict__ al)
{
    const long long row = blockIdx.x;
    const float* p = e + row * (long long)NPIX;
    const int tid = threadIdx.x;

    float v[16];
#pragma unroll
    for (int k = 0; k < 16; k++) v[k] = p[tid + k * 256];

    float mx = -1e30f;
#pragma unroll
    for (int k = 0; k < 16; k++) mx = fmaxf(mx, v[k]);
#pragma unroll
    for (int o = 16; o > 0; o >>= 1) mx = fmaxf(mx, __shfl_xor_sync(0xffffffffu, mx, o));

    __shared__ float redm[8], reds[8];
    if ((tid & 31) == 0) redm[tid >> 5] = mx;
    __syncthreads();
    mx = redm[0];
#pragma unroll
    for (int i = 1; i < 8; i++) mx = fmaxf(mx, redm[i]);

    float s = 0.f;
#pragma unroll
    for (int k = 0; k < 16; k++) { v[k] = __expf(v[k] - mx); s += v[k]; }
#pragma unroll
    for (int o = 16; o > 0; o >>= 1) s += __shfl_xor_sync(0xffffffffu, s, o);
    if ((tid & 31) == 0) reds[tid >> 5] = s;
    __syncthreads();
    s = 0.f;
#pragma unroll
    for (int i = 0; i < 8; i++) s += reds[i];

    const float inv = 1.f / s;
    __nv_bfloat16* ph = ah + row * (long long)NPIX;
    __nv_bfloat16* pl = al + row * (long long)NPIX;
#pragma unroll
    for (int k = 0; k < 16; k++) {
        float a = v[k] * inv;
        __nv_bfloat16 hi = __float2bfloat16(a);
        ph[tid + k * 256] = hi;
        pl[tid + k * 256] = __float2bfloat16(a - __bfloat162float(hi));
    }
}

// ---------------------------------------------------------------------------
extern "C" void kernel_launch(void* const* d_in, const int* in_sizes, int n_in,
                              void* d_out, int out_size)
{
    const float* x     = (const float*)d_in[0];
    const float* dep   = (const float*)d_in[1];
    const float* wq    = (const float*)d_in[2];
    const float* bq    = (const float*)d_in[3];
    const float* wqd   = (const float*)d_in[4];
    const float* bqd   = (const float*)d_in[5];
    const float* wk    = (const float*)d_in[6];
    const float* bk    = (const float*)d_in[7];
    const float* wkd   = (const float*)d_in[8];
    const float* bkd   = (const float*)d_in[9];
    const float* wv    = (const float*)d_in[10];
    const float* bv    = (const float*)d_in[11];
    const float* gamma = (const float*)d_in[12];
    float* out = (float*)d_out;

    float *qp, *kp, *ep;
    __nv_bfloat16 *qh, *ql, *kh, *kl, *ahp, *alp, *vhp, *vlp;
    cudaGetSymbolAddress((void**)&qp, g_q);
    cudaGetSymbolAddress((void**)&kp, g_k);
    cudaGetSymbolAddress((void**)&ep, g_e);
    cudaGetSymbolAddress((void**)&qh, g_qh);
    cudaGetSymbolAddress((void**)&ql, g_ql);
    cudaGetSymbolAddress((void**)&kh, g_kh);
    cudaGetSymbolAddress((void**)&kl, g_kl);
    cudaGetSymbolAddress((void**)&ahp, g_ah);
    cudaGetSymbolAddress((void**)&alp, g_al);
    cudaGetSymbolAddress((void**)&vhp, g_vh);
    cudaGetSymbolAddress((void**)&vlp, g_vl);

    const long long sIn = (long long)CCH * NPIX;
    const long long sQK = (long long)DQK * NPIX;
    const long long sE  = (long long)NPIX * NPIX;

    cudaFuncSetAttribute(mma_gemm<0>, cudaFuncAttributeMaxDynamicSharedMemorySize,
                         MMASMEM);
    cudaFuncSetAttribute(mma_gemm<2>, cudaFuncAttributeMaxDynamicSharedMemorySize,
                         MMASMEM);

    dim3 blk(256);

    // ---- q/k projections: one launch, 4 GEMMs ----
    {
        QKTab tab;
        tab.W[0] = wq;  tab.S[0] = x;   tab.bias[0] = bq;  tab.D[0] = qp;
        tab.W[1] = wqd; tab.S[1] = dep; tab.bias[1] = bqd; tab.D[1] = qp + (long long)CQ * NPIX;
        tab.W[2] = wk;  tab.S[2] = x;   tab.bias[2] = bk;  tab.D[2] = kp;
        tab.W[3] = wkd; tab.S[3] = dep; tab.bias[3] = bkd; tab.D[3] = kp + (long long)CQ * NPIX;
        dim3 gq(NPIX / 64, 4, BATCH);
        gemm_qk<<<gq, blk>>>(tab);
    }

    // ---- v projection: fp32 GEMM, bf16 hi/lo epilogue ----
    {
        dim3 gv(NPIX / 128, CCH / 64, BATCH);
        gemm_k<64, 128, 16, 4, 8, 3><<<gv, blk>>>(
            wv, x, nullptr, CCH, CCH, NPIX, NPIX, 0, sIn, sIn, bv, vhp, vlp);
    }

    // ---- q/k transpose + split ----
    {
        dim3 gt(NPIX / 32, DQK / 32, BATCH);
        tsplit_k<<<gt, blk>>>(qp, qh, ql);
        tsplit_k<<<gt, blk>>>(kp, kh, kl);
    }

    // ---- energy: bf16x3 HMMA interleaved, K=128 ----
    {
        dim3 ge(NPIX / 128, NPIX / 128, BATCH);
        mma_gemm<0><<<ge, blk, MMASMEM>>>(
            qh, ql, kh, kl, ep, DQK, sQK, sQK, sE, nullptr, nullptr);
    }

    // ---- softmax -> attn hi/lo bf16 ----
    softmax_k<<<BATCH * NPIX, blk>>>(ep, ahp, alp);

    // ---- out: bf16x3 HMMA interleaved, K=4096, epilogue gamma*acc + x ----
    {
        dim3 go(CCH / 128, NPIX / 128, BATCH);
        mma_gemm<2><<<go, blk, MMASMEM>>>(
            vhp, vlp, ahp, alp, out, NPIX, sIn, sE, sIn, x, gamma);
    }
}